// round 1
// baseline (speedup 1.0000x reference)
#include <cuda_runtime.h>

#define SQ 2048
#define NB 4
#define DM 1024
#define DI 64

// Scratch (allocation-free rule: __device__ globals)
__device__ float g_Q[NB * SQ * DI];     // (b, s, 64), pre-scaled by 1/8
__device__ float g_K[NB * SQ * DI];     // (b, s, 64)
__device__ float g_V[NB * SQ * DM];     // (b, s, 1024)
__device__ float g_inv[NB * SQ];        // 1/(1e-9 + colsum) per (b, k)

// ---------------------------------------------------------------------------
// Projection: Out[b*SQ+s][n] = (X[s*NB+b][:] @ W[:, n] + bias[n]) * scale
// X: (S, B, DM) row-major. W: (DM, N) row-major. which: 0=Q, 1=K, 2=V.
// Tile 64x64, 256 threads, 4x4 micro-tile, K-chunk 16.
// ---------------------------------------------------------------------------
__global__ void proj_kernel(const float* __restrict__ X,
                            const float* __restrict__ W,
                            const float* __restrict__ bias,
                            int which, int N, float scale) {
    __shared__ float As[16][65];
    __shared__ float Bs[16][65];
    float* Out = (which == 0) ? g_Q : (which == 1) ? g_K : g_V;

    int tid = threadIdx.x;
    int tx = tid & 15, ty = tid >> 4;
    int m0 = blockIdx.x * 64;
    int n0 = blockIdx.y * 64;

    float acc[4][4];
#pragma unroll
    for (int i = 0; i < 4; i++)
#pragma unroll
        for (int j = 0; j < 4; j++) acc[i][j] = 0.f;

    for (int k0 = 0; k0 < DM; k0 += 16) {
#pragma unroll
        for (int i = 0; i < 4; i++) {
            int e = tid + 256 * i;
            int m = e >> 4, kk = e & 15;
            int r = m0 + m;            // output row = b*SQ + s
            int b = r >> 11;
            int s = r & (SQ - 1);
            As[kk][m] = X[(s * NB + b) * DM + k0 + kk];
        }
#pragma unroll
        for (int i = 0; i < 4; i++) {
            int e = tid + 256 * i;
            int n = e & 63, kk = e >> 6;
            Bs[kk][n] = W[(k0 + kk) * N + n0 + n];
        }
        __syncthreads();
#pragma unroll
        for (int kk = 0; kk < 16; kk++) {
            float a[4], bb[4];
#pragma unroll
            for (int i = 0; i < 4; i++) a[i] = As[kk][ty * 4 + i];
#pragma unroll
            for (int j = 0; j < 4; j++) bb[j] = Bs[kk][tx * 4 + j];
#pragma unroll
            for (int i = 0; i < 4; i++)
#pragma unroll
                for (int j = 0; j < 4; j++) acc[i][j] += a[i] * bb[j];
        }
        __syncthreads();
    }
#pragma unroll
    for (int i = 0; i < 4; i++) {
        int m = m0 + ty * 4 + i;
#pragma unroll
        for (int j = 0; j < 4; j++) {
            int n = n0 + tx * 4 + j;
            Out[(size_t)m * N + n] = (acc[i][j] + bias[n]) * scale;
        }
    }
}

// ---------------------------------------------------------------------------
// Scores: probs[b][q][k] = dot64(Qs[b][q], K[b][k])  (Q already scaled by 1/8)
// ---------------------------------------------------------------------------
__global__ void scores_kernel(float* __restrict__ probs) {
    __shared__ float As[16][65];
    __shared__ float Bs[16][65];
    int b = blockIdx.z;
    const float* Q = g_Q + (size_t)b * SQ * DI;
    const float* K = g_K + (size_t)b * SQ * DI;

    int tid = threadIdx.x;
    int tx = tid & 15, ty = tid >> 4;
    int m0 = blockIdx.x * 64;
    int n0 = blockIdx.y * 64;

    float acc[4][4];
#pragma unroll
    for (int i = 0; i < 4; i++)
#pragma unroll
        for (int j = 0; j < 4; j++) acc[i][j] = 0.f;

    for (int k0 = 0; k0 < DI; k0 += 16) {
#pragma unroll
        for (int i = 0; i < 4; i++) {
            int e = tid + 256 * i;
            int m = e >> 4, kk = e & 15;
            As[kk][m] = Q[(m0 + m) * DI + k0 + kk];
            Bs[kk][m] = K[(n0 + m) * DI + k0 + kk];
        }
        __syncthreads();
#pragma unroll
        for (int kk = 0; kk < 16; kk++) {
            float a[4], bb[4];
#pragma unroll
            for (int i = 0; i < 4; i++) a[i] = As[kk][ty * 4 + i];
#pragma unroll
            for (int j = 0; j < 4; j++) bb[j] = Bs[kk][tx * 4 + j];
#pragma unroll
            for (int i = 0; i < 4; i++)
#pragma unroll
                for (int j = 0; j < 4; j++) acc[i][j] += a[i] * bb[j];
        }
        __syncthreads();
    }
#pragma unroll
    for (int i = 0; i < 4; i++) {
        int q = m0 + ty * 4 + i;
#pragma unroll
        for (int j = 0; j < 4; j++) {
            int k = n0 + tx * 4 + j;
            probs[((size_t)b * SQ + q) * SQ + k] = acc[i][j];
        }
    }
}

// ---------------------------------------------------------------------------
// Row softmax in place over last axis (2048 elems), one block per row.
// ---------------------------------------------------------------------------
__global__ void softmax_kernel(float* __restrict__ probs) {
    __shared__ float red[256];
    int row = blockIdx.x;  // b*SQ + q
    float* p = probs + (size_t)row * SQ;
    int tid = threadIdx.x;

    float mx = -1e30f;
    for (int k = tid; k < SQ; k += 256) mx = fmaxf(mx, p[k]);
    red[tid] = mx;
    __syncthreads();
    for (int s = 128; s > 0; s >>= 1) {
        if (tid < s) red[tid] = fmaxf(red[tid], red[tid + s]);
        __syncthreads();
    }
    mx = red[0];
    __syncthreads();

    float sum = 0.f;
    for (int k = tid; k < SQ; k += 256) {
        float e = __expf(p[k] - mx);
        p[k] = e;
        sum += e;
    }
    red[tid] = sum;
    __syncthreads();
    for (int s = 128; s > 0; s >>= 1) {
        if (tid < s) red[tid] += red[tid + s];
        __syncthreads();
    }
    float inv = 1.f / red[0];
    for (int k = tid; k < SQ; k += 256) p[k] *= inv;
}

// ---------------------------------------------------------------------------
// Column sum over q per (b, k): g_inv = 1/(1e-9 + sum_q probs[b][q][k])
// ---------------------------------------------------------------------------
__global__ void colsum_kernel(const float* __restrict__ probs) {
    int b = blockIdx.y;
    int k = blockIdx.x * 256 + threadIdx.x;
    const float* p = probs + (size_t)b * SQ * SQ + k;
    float sum = 0.f;
    for (int q = 0; q < SQ; q++) sum += p[(size_t)q * SQ];
    g_inv[b * SQ + k] = 1.f / (1e-9f + sum);
}

// ---------------------------------------------------------------------------
// In-place renormalization: probs[b][q][k] *= g_inv[b][k]
// ---------------------------------------------------------------------------
__global__ void normalize_kernel(float* __restrict__ probs) {
    size_t i = (size_t)blockIdx.x * 256 + threadIdx.x;  // over NB*SQ*SQ
    int k = (int)(i & (SQ - 1));
    int b = (int)(i >> 22);  // / (SQ*SQ) = / 4194304
    probs[i] *= g_inv[b * SQ + k];
}

// ---------------------------------------------------------------------------
// aten[s][b][d] = sum_k probs[b][s][k] * V[b][k][d]
// Per batch: (2048x2048) @ (2048x1024). Tile 64x64, 4x4 per thread.
// ---------------------------------------------------------------------------
__global__ void aten_kernel(const float* __restrict__ probs,
                            float* __restrict__ out) {
    __shared__ float As[16][65];
    __shared__ float Bs[16][65];
    int b = blockIdx.z;
    const float* P = probs + (size_t)b * SQ * SQ;
    const float* V = g_V + (size_t)b * SQ * DM;

    int tid = threadIdx.x;
    int tx = tid & 15, ty = tid >> 4;
    int m0 = blockIdx.x * 64;
    int n0 = blockIdx.y * 64;

    float acc[4][4];
#pragma unroll
    for (int i = 0; i < 4; i++)
#pragma unroll
        for (int j = 0; j < 4; j++) acc[i][j] = 0.f;

    for (int k0 = 0; k0 < SQ; k0 += 16) {
#pragma unroll
        for (int i = 0; i < 4; i++) {
            int e = tid + 256 * i;
            int m = e >> 4, kk = e & 15;
            As[kk][m] = P[(size_t)(m0 + m) * SQ + k0 + kk];
        }
#pragma unroll
        for (int i = 0; i < 4; i++) {
            int e = tid + 256 * i;
            int n = e & 63, kk = e >> 6;
            Bs[kk][n] = V[(size_t)(k0 + kk) * DM + n0 + n];
        }
        __syncthreads();
#pragma unroll
        for (int kk = 0; kk < 16; kk++) {
            float a[4], bb[4];
#pragma unroll
            for (int i = 0; i < 4; i++) a[i] = As[kk][ty * 4 + i];
#pragma unroll
            for (int j = 0; j < 4; j++) bb[j] = Bs[kk][tx * 4 + j];
#pragma unroll
            for (int i = 0; i < 4; i++)
#pragma unroll
                for (int j = 0; j < 4; j++) acc[i][j] += a[i] * bb[j];
        }
        __syncthreads();
    }
#pragma unroll
    for (int i = 0; i < 4; i++) {
        int q = m0 + ty * 4 + i;
#pragma unroll
        for (int j = 0; j < 4; j++) {
            int d = n0 + tx * 4 + j;
            out[((size_t)q * NB + b) * DM + d] = acc[i][j];
        }
    }
}

// ---------------------------------------------------------------------------
extern "C" void kernel_launch(void* const* d_in, const int* in_sizes, int n_in,
                              void* d_out, int out_size) {
    const float* query = (const float*)d_in[0];
    const float* key   = (const float*)d_in[1];
    const float* value = (const float*)d_in[2];
    const float* Wq    = (const float*)d_in[3];
    const float* bq    = (const float*)d_in[4];
    const float* Wk    = (const float*)d_in[5];
    const float* bk    = (const float*)d_in[6];
    const float* Wv    = (const float*)d_in[7];
    const float* bv    = (const float*)d_in[8];

    float* aten  = (float*)d_out;                            // S*B*D floats
    float* probs = (float*)d_out + (size_t)SQ * NB * DM;     // B*S*S floats

    dim3 blk(256);
    const float qscale = 0.125f;  // 1/sqrt(64)

    // Projections
    proj_kernel<<<dim3((NB * SQ) / 64, DI / 64), blk>>>(query, Wq, bq, 0, DI, qscale);
    proj_kernel<<<dim3((NB * SQ) / 64, DI / 64), blk>>>(key,   Wk, bk, 1, DI, 1.0f);
    proj_kernel<<<dim3((NB * SQ) / 64, DM / 64), blk>>>(value, Wv, bv, 2, DM, 1.0f);

    // Scores into probs region
    scores_kernel<<<dim3(SQ / 64, SQ / 64, NB), blk>>>(probs);

    // Softmax over keys, per row
    softmax_kernel<<<NB * SQ, blk>>>(probs);

    // Renormalize over query axis
    colsum_kernel<<<dim3(SQ / 256, NB), blk>>>(probs);
    normalize_kernel<<<(unsigned)(((size_t)NB * SQ * SQ) / 256), blk>>>(probs);

    // Attention output (transposed write to (S, B, D))
    aten_kernel<<<dim3(SQ / 64, DM / 64, NB), blk>>>(probs, aten);
}

// round 3
// speedup vs baseline: 2.2634x; 2.2634x over previous
#include <cuda_runtime.h>
#include <cuda_bf16.h>
#include <cstdint>

#define SQ 2048
#define NB 4
#define DM 1024
#define DI 64

typedef __nv_bfloat16 bf16;

// ---------------------------------------------------------------------------
// Device scratch (allocation-free rule: __device__ globals)
// ---------------------------------------------------------------------------
__device__ __align__(16) float g_V[(size_t)NB * SQ * DM];     // V proj fp32 (b,k,d)
__device__ float g_inv[NB * SQ];
__device__ __align__(16) bf16 g_Wqt_h[DI * DM];               // Wq^T (n,k) hi/lo
__device__ __align__(16) bf16 g_Wqt_l[DI * DM];
__device__ __align__(16) bf16 g_Wkt_h[DI * DM];
__device__ __align__(16) bf16 g_Wkt_l[DI * DM];
__device__ __align__(16) bf16 g_Wvt_h[DM * DM];               // Wv^T (n,k)
__device__ __align__(16) bf16 g_Wvt_l[DM * DM];
__device__ __align__(16) bf16 g_Qh[NB * SQ * DI];             // Q proj hi/lo (scaled)
__device__ __align__(16) bf16 g_Ql[NB * SQ * DI];
__device__ __align__(16) bf16 g_Kh[NB * SQ * DI];             // K proj hi/lo
__device__ __align__(16) bf16 g_Kl[NB * SQ * DI];
__device__ __align__(16) bf16 g_Vth[(size_t)NB * DM * SQ];    // V^T (b,d,k) hi/lo
__device__ __align__(16) bf16 g_Vtl[(size_t)NB * DM * SQ];
__device__ __align__(16) bf16 g_Ph[(size_t)NB * SQ * SQ];     // probs hi/lo
__device__ __align__(16) bf16 g_Pl[(size_t)NB * SQ * SQ];

// ---------------------------------------------------------------------------
// MMA / ldmatrix helpers (all supported on plain compute_103)
// ---------------------------------------------------------------------------
__device__ __forceinline__ uint32_t smem_u32(const void* p) {
    uint32_t a;
    asm("{ .reg .u64 t; cvta.to.shared.u64 t, %1; cvt.u32.u64 %0, t; }"
        : "=r"(a) : "l"(p));
    return a;
}

__device__ __forceinline__ void ldsm4(uint32_t& r0, uint32_t& r1, uint32_t& r2,
                                      uint32_t& r3, uint32_t addr) {
    asm volatile("ldmatrix.sync.aligned.m8n8.x4.shared.b16 {%0,%1,%2,%3}, [%4];"
                 : "=r"(r0), "=r"(r1), "=r"(r2), "=r"(r3) : "r"(addr));
}

__device__ __forceinline__ void mma16816(float c[4], const uint32_t a[4],
                                         const uint32_t b[2]) {
    asm volatile(
        "mma.sync.aligned.m16n8k16.row.col.f32.bf16.bf16.f32 "
        "{%0,%1,%2,%3}, {%4,%5,%6,%7}, {%8,%9}, {%0,%1,%2,%3};"
        : "+f"(c[0]), "+f"(c[1]), "+f"(c[2]), "+f"(c[3])
        : "r"(a[0]), "r"(a[1]), "r"(a[2]), "r"(a[3]), "r"(b[0]), "r"(b[1]));
}

__device__ __forceinline__ uint32_t pack2(bf16 a, bf16 b) {
    return (uint32_t)__bfloat16_as_ushort(a) |
           ((uint32_t)__bfloat16_as_ushort(b) << 16);
}

// 16B-chunk swizzle for 64B rows: phys_chunk = c ^ ((row>>1)&3)
// (conflict-free across each 8-lane LDSM phase: even/odd rows split the
//  128B halves, (row>>1)&3 makes the 4 chunks distinct within each half)
__device__ __forceinline__ uint32_t swz(int row, int chunk) {
    return (uint32_t)(row * 64 + ((chunk ^ ((row >> 1) & 3)) * 16));
}

// ---------------------------------------------------------------------------
// Compensated-bf16 GEMM via mma.sync.
//   D[m,n] = sum_k A[m,k]*B[n,k]   (both operands K-major rows)
//   CTA tile 128 x BN, BK=32, 8 warps (4x2), warp tile 32 x BN/2.
//   AMODE: 0 = fp32 A with (S,B,D)->(b,s) gather + on-the-fly hi/lo split
//          1 = fp32 A direct + on-the-fly split
//          2 = pre-split bf16 A (Ah/Al)
//   Epilogue: v=(acc+bias)*scale -> fp32 out (if outf) and/or bf16 hi/lo (oh/ol)
// ---------------------------------------------------------------------------
template <int BN, int AMODE>
__global__ void __launch_bounds__(256, 1)
gemm_mma(const float* __restrict__ Af,
         const bf16* __restrict__ Ah, const bf16* __restrict__ Al,
         size_t sAz, int lda,
         const bf16* __restrict__ Bh, const bf16* __restrict__ Bl,
         size_t sBz, int ldb,
         float* __restrict__ outf, bf16* __restrict__ oh, bf16* __restrict__ ol,
         size_t sOz, int ldo,
         const float* __restrict__ bias, float scale, int K) {
    constexpr int WN = BN / 2;      // warp N extent
    constexpr int NT = WN / 8;      // n8 tiles per warp

    __shared__ __align__(128) bf16 sAh[128 * 32];
    __shared__ __align__(128) bf16 sAl[128 * 32];
    __shared__ __align__(128) bf16 sBh[BN * 32];
    __shared__ __align__(128) bf16 sBl[BN * 32];

    const int tid = threadIdx.x, wid = tid >> 5, lane = tid & 31;
    const int wm = wid >> 1, wn = wid & 1;
    const int z = blockIdx.z;
    const int m0 = blockIdx.x * 128, n0 = blockIdx.y * BN;

    if (AMODE == 2) { Ah += (size_t)z * sAz; Al += (size_t)z * sAz; }
    else            { Af += (size_t)z * sAz; }
    Bh += (size_t)z * sBz;
    Bl += (size_t)z * sBz;

    float c[2][NT][4];
#pragma unroll
    for (int mi = 0; mi < 2; mi++)
#pragma unroll
        for (int nj = 0; nj < NT; nj++)
#pragma unroll
            for (int t = 0; t < 4; t++) c[mi][nj][t] = 0.f;

    const uint32_t aH = smem_u32(sAh), aL = smem_u32(sAl);
    const uint32_t bH = smem_u32(sBh), bL = smem_u32(sBl);

    for (int kt = 0; kt < K; kt += 32) {
        // ---- stage A (128 x 32) ----
        if (AMODE == 2) {
#pragma unroll
            for (int i = 0; i < 2; i++) {
                int idx = tid + 256 * i;           // 512 16B chunks, 4/row
                int r = idx >> 2, cc = idx & 3;
                size_t go = (size_t)(m0 + r) * lda + kt + cc * 8;
                uint32_t d = swz(r, cc);
                *(uint4*)((char*)sAh + d) = *(const uint4*)(Ah + go);
                *(uint4*)((char*)sAl + d) = *(const uint4*)(Al + go);
            }
        } else {
#pragma unroll
            for (int i = 0; i < 4; i++) {
                int idx = tid + 256 * i;           // 1024 float4 slots, 8/row
                int r = idx >> 3, slot = idx & 7;
                int m = m0 + r;
                int gr = (AMODE == 0) ? ((m & (SQ - 1)) * NB + (m >> 11)) : m;
                float4 v = *(const float4*)(Af + (size_t)gr * lda + kt + slot * 4);
                bf16 h0 = __float2bfloat16(v.x);
                bf16 h1 = __float2bfloat16(v.y);
                bf16 h2 = __float2bfloat16(v.z);
                bf16 h3 = __float2bfloat16(v.w);
                bf16 l0 = __float2bfloat16(v.x - __bfloat162float(h0));
                bf16 l1 = __float2bfloat16(v.y - __bfloat162float(h1));
                bf16 l2 = __float2bfloat16(v.z - __bfloat162float(h2));
                bf16 l3 = __float2bfloat16(v.w - __bfloat162float(h3));
                uint32_t d = swz(r, slot >> 1) + (slot & 1) * 8;
                *(uint2*)((char*)sAh + d) = make_uint2(pack2(h0, h1), pack2(h2, h3));
                *(uint2*)((char*)sAl + d) = make_uint2(pack2(l0, l1), pack2(l2, l3));
            }
        }
        // ---- stage B (BN x 32) ----
#pragma unroll
        for (int i = 0; i < BN / 64; i++) {
            int idx = tid + 256 * i;
            int r = idx >> 2, cc = idx & 3;
            size_t go = (size_t)(n0 + r) * ldb + kt + cc * 8;
            uint32_t d = swz(r, cc);
            *(uint4*)((char*)sBh + d) = *(const uint4*)(Bh + go);
            *(uint4*)((char*)sBl + d) = *(const uint4*)(Bl + go);
        }
        __syncthreads();

#pragma unroll
        for (int ks = 0; ks < 2; ks++) {
            // A fragments (two m16 tiles, hi & lo)
            uint32_t ah[2][4], al[2][4];
#pragma unroll
            for (int mi = 0; mi < 2; mi++) {
                int row = wm * 32 + mi * 16 + (lane & 15);
                int chunk = ks * 2 + (lane >> 4);
                uint32_t off = swz(row, chunk);
                ldsm4(ah[mi][0], ah[mi][1], ah[mi][2], ah[mi][3], aH + off);
                ldsm4(al[mi][0], al[mi][1], al[mi][2], al[mi][3], aL + off);
            }
            // B fragments (NT n8 tiles, loaded 2 at a time, hi & lo)
            uint32_t bh[NT][2], bl[NT][2];
#pragma unroll
            for (int nj = 0; nj < NT; nj += 2) {
                int n = wn * WN + nj * 8 + ((lane >> 4) << 3) + (lane & 7);
                int chunk = ks * 2 + ((lane >> 3) & 1);
                uint32_t off = swz(n, chunk);
                uint32_t r0, r1, r2, r3;
                ldsm4(r0, r1, r2, r3, bH + off);
                bh[nj][0] = r0; bh[nj][1] = r1;
                bh[nj + 1][0] = r2; bh[nj + 1][1] = r3;
                ldsm4(r0, r1, r2, r3, bL + off);
                bl[nj][0] = r0; bl[nj][1] = r1;
                bl[nj + 1][0] = r2; bl[nj + 1][1] = r3;
            }
#pragma unroll
            for (int mi = 0; mi < 2; mi++)
#pragma unroll
                for (int nj = 0; nj < NT; nj++) {
                    mma16816(c[mi][nj], ah[mi], bh[nj]);
                    mma16816(c[mi][nj], ah[mi], bl[nj]);
                    mma16816(c[mi][nj], al[mi], bh[nj]);
                }
        }
        __syncthreads();
    }

    // ---- epilogue ----
#pragma unroll
    for (int mi = 0; mi < 2; mi++) {
        int r0 = m0 + wm * 32 + mi * 16 + (lane >> 2);
#pragma unroll
        for (int nj = 0; nj < NT; nj++) {
            int col = n0 + wn * WN + nj * 8 + (lane & 3) * 2;
            float b0 = bias ? bias[col] : 0.f;
            float b1 = bias ? bias[col + 1] : 0.f;
            float v00 = (c[mi][nj][0] + b0) * scale;
            float v01 = (c[mi][nj][1] + b1) * scale;
            float v10 = (c[mi][nj][2] + b0) * scale;
            float v11 = (c[mi][nj][3] + b1) * scale;
            if (outf) {
                float* o = outf + (size_t)z * sOz;
                o[(size_t)r0 * ldo + col] = v00;
                o[(size_t)r0 * ldo + col + 1] = v01;
                o[(size_t)(r0 + 8) * ldo + col] = v10;
                o[(size_t)(r0 + 8) * ldo + col + 1] = v11;
            }
            if (oh) {
                bf16* ph = oh + (size_t)z * sOz;
                bf16* pl = ol + (size_t)z * sOz;
                size_t i00 = (size_t)r0 * ldo + col;
                size_t i10 = (size_t)(r0 + 8) * ldo + col;
                bf16 h;
                h = __float2bfloat16(v00); ph[i00] = h;
                pl[i00] = __float2bfloat16(v00 - __bfloat162float(h));
                h = __float2bfloat16(v01); ph[i00 + 1] = h;
                pl[i00 + 1] = __float2bfloat16(v01 - __bfloat162float(h));
                h = __float2bfloat16(v10); ph[i10] = h;
                pl[i10] = __float2bfloat16(v10 - __bfloat162float(h));
                h = __float2bfloat16(v11); ph[i10 + 1] = h;
                pl[i10 + 1] = __float2bfloat16(v11 - __bfloat162float(h));
            }
        }
    }
}

// ---------------------------------------------------------------------------
// Transpose + hi/lo split: src fp32 [R x C] (+z*R*C) -> dst bf16 [C x R]
// ---------------------------------------------------------------------------
__global__ void transpose_convert(const float* __restrict__ src,
                                  bf16* __restrict__ dh, bf16* __restrict__ dl,
                                  int R, int C) {
    __shared__ float t[32][33];
    int z = blockIdx.z;
    src += (size_t)z * R * C;
    dh += (size_t)z * R * C;
    dl += (size_t)z * R * C;
    int c0 = blockIdx.x * 32, r0 = blockIdx.y * 32;
    int tx = threadIdx.x, ty = threadIdx.y;  // (32, 8)
#pragma unroll
    for (int i = 0; i < 32; i += 8)
        t[ty + i][tx] = src[(size_t)(r0 + ty + i) * C + c0 + tx];
    __syncthreads();
#pragma unroll
    for (int i = 0; i < 32; i += 8) {
        float v = t[tx][ty + i];
        bf16 h = __float2bfloat16(v);
        size_t o = (size_t)(c0 + ty + i) * R + r0 + tx;
        dh[o] = h;
        dl[o] = __float2bfloat16(v - __bfloat162float(h));
    }
}

// ---------------------------------------------------------------------------
// Softmax chain
// ---------------------------------------------------------------------------
__global__ void softmax_kernel(float* __restrict__ probs) {
    __shared__ float red[256];
    int row = blockIdx.x;
    float* p = probs + (size_t)row * SQ;
    int tid = threadIdx.x;

    float mx = -1e30f;
    for (int k = tid; k < SQ; k += 256) mx = fmaxf(mx, p[k]);
    red[tid] = mx;
    __syncthreads();
    for (int s = 128; s > 0; s >>= 1) {
        if (tid < s) red[tid] = fmaxf(red[tid], red[tid + s]);
        __syncthreads();
    }
    mx = red[0];
    __syncthreads();

    float sum = 0.f;
    for (int k = tid; k < SQ; k += 256) {
        float e = __expf(p[k] - mx);
        p[k] = e;
        sum += e;
    }
    red[tid] = sum;
    __syncthreads();
    for (int s = 128; s > 0; s >>= 1) {
        if (tid < s) red[tid] += red[tid + s];
        __syncthreads();
    }
    float inv = 1.f / red[0];
    for (int k = tid; k < SQ; k += 256) p[k] *= inv;
}

__global__ void colsum_kernel(const float* __restrict__ probs) {
    int b = blockIdx.y;
    int k = blockIdx.x * 256 + threadIdx.x;
    const float* p = probs + (size_t)b * SQ * SQ + k;
    float sum = 0.f;
    for (int q = 0; q < SQ; q++) sum += p[(size_t)q * SQ];
    g_inv[b * SQ + k] = 1.f / (1e-9f + sum);
}

// normalize + emit probs hi/lo for the aten GEMM
__global__ void normalize_kernel(float* __restrict__ probs) {
    size_t i = (size_t)blockIdx.x * 256 + threadIdx.x;
    int k = (int)(i & (SQ - 1));
    int b = (int)(i >> 22);
    float v = probs[i] * g_inv[b * SQ + k];
    probs[i] = v;
    bf16 h = __float2bfloat16(v);
    g_Ph[i] = h;
    g_Pl[i] = __float2bfloat16(v - __bfloat162float(h));
}

// ---------------------------------------------------------------------------
extern "C" void kernel_launch(void* const* d_in, const int* in_sizes, int n_in,
                              void* d_out, int out_size) {
    const float* query = (const float*)d_in[0];
    const float* key   = (const float*)d_in[1];
    const float* value = (const float*)d_in[2];
    const float* Wq    = (const float*)d_in[3];
    const float* bq    = (const float*)d_in[4];
    const float* Wk    = (const float*)d_in[5];
    const float* bk    = (const float*)d_in[6];
    const float* Wv    = (const float*)d_in[7];
    const float* bv    = (const float*)d_in[8];

    float* aten  = (float*)d_out;
    float* probs = (float*)d_out + (size_t)SQ * NB * DM;

    void *pV, *pWqh, *pWql, *pWkh, *pWkl, *pWvh, *pWvl;
    void *pQh, *pQl, *pKh, *pKl, *pVth, *pVtl, *pPh, *pPl;
    cudaGetSymbolAddress(&pV, g_V);
    cudaGetSymbolAddress(&pWqh, g_Wqt_h);
    cudaGetSymbolAddress(&pWql, g_Wqt_l);
    cudaGetSymbolAddress(&pWkh, g_Wkt_h);
    cudaGetSymbolAddress(&pWkl, g_Wkt_l);
    cudaGetSymbolAddress(&pWvh, g_Wvt_h);
    cudaGetSymbolAddress(&pWvl, g_Wvt_l);
    cudaGetSymbolAddress(&pQh, g_Qh);
    cudaGetSymbolAddress(&pQl, g_Ql);
    cudaGetSymbolAddress(&pKh, g_Kh);
    cudaGetSymbolAddress(&pKl, g_Kl);
    cudaGetSymbolAddress(&pVth, g_Vth);
    cudaGetSymbolAddress(&pVtl, g_Vtl);
    cudaGetSymbolAddress(&pPh, g_Ph);
    cudaGetSymbolAddress(&pPl, g_Pl);

    dim3 t256(256);
    dim3 tT(32, 8);

    // 1) weights -> W^T hi/lo
    transpose_convert<<<dim3(DI / 32, DM / 32, 1), tT>>>(
        Wq, (bf16*)pWqh, (bf16*)pWql, DM, DI);
    transpose_convert<<<dim3(DI / 32, DM / 32, 1), tT>>>(
        Wk, (bf16*)pWkh, (bf16*)pWkl, DM, DI);
    transpose_convert<<<dim3(DM / 32, DM / 32, 1), tT>>>(
        Wv, (bf16*)pWvh, (bf16*)pWvl, DM, DM);

    // 2) projections: Q,K write hi/lo directly; V writes fp32
    gemm_mma<64, 0><<<dim3(64, 1, 1), t256>>>(
        query, nullptr, nullptr, 0, DM,
        (bf16*)pWqh, (bf16*)pWql, 0, DM,
        nullptr, (bf16*)pQh, (bf16*)pQl, 0, DI, bq, 0.125f, DM);
    gemm_mma<64, 0><<<dim3(64, 1, 1), t256>>>(
        key, nullptr, nullptr, 0, DM,
        (bf16*)pWkh, (bf16*)pWkl, 0, DM,
        nullptr, (bf16*)pKh, (bf16*)pKl, 0, DI, bk, 1.0f, DM);
    gemm_mma<128, 0><<<dim3(64, 8, 1), t256>>>(
        value, nullptr, nullptr, 0, DM,
        (bf16*)pWvh, (bf16*)pWvl, 0, DM,
        (float*)pV, nullptr, nullptr, 0, DM, bv, 1.0f, DM);

    // 3) V -> V^T (b,d,k) hi/lo
    transpose_convert<<<dim3(DM / 32, SQ / 32, NB), tT>>>(
        (const float*)pV, (bf16*)pVth, (bf16*)pVtl, SQ, DM);

    // 4) scores: probs[b,q,k'] = Q[b,q,:] . K[b,k',:]
    gemm_mma<128, 2><<<dim3(16, 16, NB), t256>>>(
        nullptr, (const bf16*)pQh, (const bf16*)pQl, (size_t)SQ * DI, DI,
        (const bf16*)pKh, (const bf16*)pKl, (size_t)SQ * DI, DI,
        probs, nullptr, nullptr, (size_t)SQ * SQ, SQ, nullptr, 1.0f, DI);

    // 5) softmax over keys + renorm over queries (+ emit probs hi/lo)
    softmax_kernel<<<NB * SQ, t256>>>(probs);
    colsum_kernel<<<dim3(SQ / 256, NB), t256>>>(probs);
    normalize_kernel<<<(unsigned)(((size_t)NB * SQ * SQ) / 256), t256>>>(probs);

    // 6) aten[q,b,d] = sum_k probs[b,q,k] * V[b,k,d]
    gemm_mma<128, 2><<<dim3(16, 8, NB), t256>>>(
        nullptr, (const bf16*)pPh, (const bf16*)pPl, (size_t)SQ * SQ, SQ,
        (const bf16*)pVth, (const bf16*)pVtl, (size_t)DM * SQ, SQ,
        aten, nullptr, nullptr, (size_t)DM, NB * DM, nullptr, 1.0f, SQ);
}